// round 1
// baseline (speedup 1.0000x reference)
#include <cuda_runtime.h>

#define NS  12
#define NC  4
#define NSC 16
#define TT  50
#define BB  2048
#define NLS 5
#define WPB 4   // warps (batch elements) per block

// ---------------- scratch (device globals; no allocation allowed) ----------
__device__ float g_KK[TT * BB * 52];          // [T,B,52]: K[u][s] at u*13+s, kk at u*13+12
__device__ float g_taus[NLS * TT * BB * 16];  // [a,T,B,16]
__device__ float g_cost[NLS * BB];
__device__ int   g_best[BB];
__device__ float g_unom[TT * BB * 4];

// ============================================================================
// Backward Riccati: one warp per batch element, t = T-1 .. 0
// ============================================================================
__global__ void __launch_bounds__(32 * WPB) riccati_kernel(
    const float* __restrict__ gC, const float* __restrict__ gc,
    const float* __restrict__ gF, const float* __restrict__ gf)
{
    __shared__ float smem[WPB][896];
    const int w = threadIdx.x >> 5;
    const int lane = threadIdx.x & 31;
    const int b = blockIdx.x * WPB + w;

    float* sF = smem[w];          // 192   F[k][j] = sF[k*16+j], k<12, j<16
    float* sQ = sF + 192;         // 256   Q (init = C)
    float* sq = sQ + 256;         // 16
    float* sf = sq + 16;          // 12
    float* sV = sf + 12;          // 144   V[k][m] = sV[k*12+m]
    float* sv = sV + 144;         // 12
    float* sW = sv + 12;          // 192   W = V F; reused as M scratch (12x12)
    float* sK = sW + 192;         // 52    K[u][s]=sK[u*13+s], kk=sK[u*13+12]
    float* sg = sK + 52;          // 12

    // init V = 0, v = 0
#pragma unroll
    for (int r = 0; r < 5; ++r) { int idx = lane + 32 * r; if (idx < 144) sV[idx] = 0.f; }
    if (lane < 12) sv[lane] = 0.f;
    __syncwarp();

    const int j = lane & 15;
    const int h = lane >> 4;

    for (int t = TT - 1; t >= 0; --t) {
        const int base = t * BB + b;
        const float* Cp = gC + (size_t)base * 256;
        const float* Fp = gF + (size_t)base * 192;
#pragma unroll
        for (int r = 0; r < 6; ++r) sF[lane + 32 * r] = Fp[lane + 32 * r];
#pragma unroll
        for (int r = 0; r < 8; ++r) sQ[lane + 32 * r] = Cp[lane + 32 * r];
        if (lane < 16) sq[lane] = gc[(size_t)base * 16 + lane];
        if (lane < 12) sf[lane] = gf[(size_t)base * 12 + lane];
        __syncwarp();

        // ---- Phase 1: W = V F   (lane = j + 16h owns W[h*6..h*6+5][j]);  g = V f + v
        {
            float acc[6] = {0.f, 0.f, 0.f, 0.f, 0.f, 0.f};
#pragma unroll
            for (int m = 0; m < 12; ++m) {
                float Fmj = sF[m * 16 + j];
#pragma unroll
                for (int kk = 0; kk < 6; ++kk)
                    acc[kk] += sV[(h * 6 + kk) * 12 + m] * Fmj;
            }
#pragma unroll
            for (int kk = 0; kk < 6; ++kk) sW[(h * 6 + kk) * 16 + j] = acc[kk];
            if (lane < 12) {
                float g = sv[lane];
#pragma unroll
                for (int m = 0; m < 12; ++m) g += sV[lane * 12 + m] * sf[m];
                sg[lane] = g;
            }
        }
        __syncwarp();

        // ---- Phase 2: Q += F^T W  (lane = j+16h owns Q[h*8..h*8+7][j]);  q += F^T g
        {
            float acc[8] = {0.f, 0.f, 0.f, 0.f, 0.f, 0.f, 0.f, 0.f};
#pragma unroll
            for (int k = 0; k < 12; ++k) {
                float Wkj = sW[k * 16 + j];
#pragma unroll
                for (int ii = 0; ii < 8; ++ii)
                    acc[ii] += sF[k * 16 + (h * 8 + ii)] * Wkj;
            }
#pragma unroll
            for (int ii = 0; ii < 8; ++ii) sQ[(h * 8 + ii) * 16 + j] += acc[ii];
            if (lane < 16) {
                float qa = sq[lane];
#pragma unroll
                for (int k = 0; k < 12; ++k) qa += sF[k * 16 + lane] * sg[k];
                sq[lane] = qa;
            }
        }
        __syncwarp();

        // ---- Phase 3: solve Quu * sol = [Qux | qu]; K = -sol (13 RHS cols, one/lane)
        {
            float A[4][4], r[4];
            const int col = (lane < 13) ? lane : 12;
#pragma unroll
            for (int u = 0; u < 4; ++u) {
#pragma unroll
                for (int w2 = 0; w2 < 4; ++w2) A[u][w2] = sQ[(12 + u) * 16 + 12 + w2];
                r[u] = (col < 12) ? sQ[(12 + u) * 16 + col] : sq[12 + u];
            }
#pragma unroll
            for (int p = 0; p < 4; ++p) {
                float inv = 1.0f / A[p][p];
                r[p] *= inv;
#pragma unroll
                for (int w2 = 0; w2 < 4; ++w2) if (w2 > p) A[p][w2] *= inv;
#pragma unroll
                for (int u = 0; u < 4; ++u) if (u > p) {
                    float mu = A[u][p];
                    r[u] -= mu * r[p];
#pragma unroll
                    for (int w2 = 0; w2 < 4; ++w2) if (w2 > p) A[u][w2] -= mu * A[p][w2];
                }
            }
#pragma unroll
            for (int p = 3; p >= 1; --p)
#pragma unroll
                for (int u = 0; u < 4; ++u) if (u < p) r[u] -= A[u][p] * r[p];
            if (lane < 13) {
#pragma unroll
                for (int u = 0; u < 4; ++u) sK[u * 13 + lane] = -r[u];
            }
        }
        __syncwarp();

        // store K/kk to global (coalesced)
        {
            const size_t kb = (size_t)base * 52;
            g_KK[kb + lane] = sK[lane];
            if (lane + 32 < 52) g_KK[kb + lane + 32] = sK[lane + 32];
        }

        // ---- Phase 4: M = Qxx + Qxu K ; V = 0.5(M+M^T) ; v = qx + K^T qu
        {
#pragma unroll
            for (int r2 = 0; r2 < 5; ++r2) {
                int idx = lane + 32 * r2;
                if (idx < 144) {
                    int i = idx / 12, jj = idx - i * 12;
                    float m = sQ[i * 16 + jj];
#pragma unroll
                    for (int u = 0; u < 4; ++u) m += sQ[i * 16 + 12 + u] * sK[u * 13 + jj];
                    sW[idx] = m;
                }
            }
            __syncwarp();
#pragma unroll
            for (int r2 = 0; r2 < 5; ++r2) {
                int idx = lane + 32 * r2;
                if (idx < 144) {
                    int i = idx / 12, jj = idx - i * 12;
                    sV[idx] = 0.5f * (sW[idx] + sW[jj * 12 + i]);
                }
            }
            if (lane < 12) {
                float vn = sq[lane];
#pragma unroll
                for (int u = 0; u < 4; ++u) vn += sK[u * 13 + lane] * sq[12 + u];
                sv[lane] = vn;
            }
        }
        __syncwarp();
    }
}

// ============================================================================
// Forward rollout: one warp per batch element, all 5 alphas simultaneously
// ============================================================================
__global__ void __launch_bounds__(32 * WPB) rollout_kernel(
    const float* __restrict__ gC, const float* __restrict__ gc,
    const float* __restrict__ gF, const float* __restrict__ gf,
    const float* __restrict__ gx0, int use_unom)
{
    __shared__ float smem[WPB][768];
    const int w = threadIdx.x >> 5;
    const int lane = threadIdx.x & 31;
    const int b = blockIdx.x * WPB + w;

    float* sF   = smem[w];        // 192
    float* sC   = sF + 192;       // 256
    float* sc   = sC + 256;       // 16
    float* sf   = sc + 16;        // 12
    float* sK   = sf + 12;        // 52
    float* sun  = sK + 52;        // 4
    float* sTau = sun + 4;        // 80  [a][16]
    float* sPart= sTau + 80;      // 80
    float* sX   = sPart + 80;     // 60  [a][12]

    if (lane < 12) {
        float x = gx0[b * 12 + lane];
#pragma unroll
        for (int a = 0; a < 5; ++a) sX[a * 12 + lane] = x;
    }
    float myCost = 0.f;
    __syncwarp();

    for (int t = 0; t < TT; ++t) {
        const int base = t * BB + b;
        const float* Cp = gC + (size_t)base * 256;
        const float* Fp = gF + (size_t)base * 192;
#pragma unroll
        for (int r = 0; r < 8; ++r) sC[lane + 32 * r] = Cp[lane + 32 * r];
#pragma unroll
        for (int r = 0; r < 6; ++r) sF[lane + 32 * r] = Fp[lane + 32 * r];
        if (lane < 16) sc[lane] = gc[(size_t)base * 16 + lane];
        if (lane < 12) sf[lane] = gf[(size_t)base * 12 + lane];
        {
            const size_t kb = (size_t)base * 52;
            sK[lane] = g_KK[kb + lane];
            if (lane + 32 < 52) sK[lane + 32] = g_KK[kb + lane + 32];
        }
        if (lane < 4) sun[lane] = use_unom ? g_unom[(size_t)base * 4 + lane] : 0.f;
        __syncwarp();

        // ---- controls: lane = a*4+u for lane<20
        if (lane < 20) {
            int a = lane >> 2, u = lane & 3;
            float ul = sK[u * 13 + 12];
#pragma unroll
            for (int s = 0; s < 12; ++s) ul += sK[u * 13 + s] * sX[a * 12 + s];
            float alpha = 1.0f / (float)(1 << a);
            float uu = (1.0f - alpha) * sun[u] + alpha * ul;
            uu = fminf(1.0f, fmaxf(-1.0f, uu));
            sTau[a * 16 + 12 + u] = uu;
        }
        // copy x part into tau
#pragma unroll
        for (int r = 0; r < 2; ++r) {
            int idx = lane + 32 * r;
            if (idx < 60) {
                int a = idx / 12, s = idx - a * 12;
                sTau[a * 16 + s] = sX[idx];
            }
        }
        __syncwarp();

        // ---- cost partials + write taus_all
#pragma unroll
        for (int r = 0; r < 3; ++r) {
            int idx = lane + 32 * r;
            if (idx < 80) {
                int a = idx >> 4, jj = idx & 15;
                float s = 0.f;
#pragma unroll
                for (int i = 0; i < 16; ++i) s += sTau[a * 16 + i] * sC[i * 16 + jj];
                float ta = sTau[a * 16 + jj];
                sPart[idx] = ta * (0.5f * s + sc[jj]);
                g_taus[((size_t)(a * TT + t) * BB + b) * 16 + jj] = ta;
            }
        }
        // ---- x_next
        float xn0 = 0.f, xn1 = 0.f;
        {
            int idx = lane;
            if (idx < 60) {
                int a = idx / 12, s = idx - a * 12;
                float v = sf[s];
#pragma unroll
                for (int jj = 0; jj < 16; ++jj) v += sF[s * 16 + jj] * sTau[a * 16 + jj];
                xn0 = v;
            }
            idx = lane + 32;
            if (idx < 60) {
                int a = idx / 12, s = idx - a * 12;
                float v = sf[s];
#pragma unroll
                for (int jj = 0; jj < 16; ++jj) v += sF[s * 16 + jj] * sTau[a * 16 + jj];
                xn1 = v;
            }
        }
        __syncwarp();

        if (lane < 5) {
            float cs = 0.f;
#pragma unroll
            for (int jj = 0; jj < 16; ++jj) cs += sPart[lane * 16 + jj];
            myCost += cs;
        }
        if (lane < 60) sX[lane] = xn0;
        if (lane + 32 < 60) sX[lane + 32] = xn1;
        __syncwarp();
    }

    if (lane < 5) g_cost[lane * BB + b] = myCost;
}

// ============================================================================
// argmin over alphas (first-min semantics, matching jnp.argmin)
// ============================================================================
__global__ void select_kernel()
{
    int b = blockIdx.x * blockDim.x + threadIdx.x;
    if (b >= BB) return;
    float best = g_cost[b];
    int bi = 0;
#pragma unroll
    for (int a = 1; a < NLS; ++a) {
        float cv = g_cost[a * BB + b];
        if (cv < best) { best = cv; bi = a; }
    }
    g_best[b] = bi;
}

// ============================================================================
// gather best taus -> u_nom (and output on final iteration)
// ============================================================================
__global__ void gather_kernel(float* __restrict__ out, int write_out)
{
    int tid = blockIdx.x * blockDim.x + threadIdx.x;
    if (tid >= TT * BB * 16) return;
    int i = tid & 15;
    int bb = (tid >> 4) & (BB - 1);
    int best = g_best[bb];
    float v = g_taus[(size_t)best * (TT * BB * 16) + tid];
    if (i >= 12) {
        int t = tid >> 15;   // 16 * 2048 = 2^15
        g_unom[((size_t)t * BB + bb) * 4 + (i - 12)] = v;
    }
    if (write_out) out[tid] = v;
}

// ============================================================================
extern "C" void kernel_launch(void* const* d_in, const int* in_sizes, int n_in,
                              void* d_out, int out_size)
{
    const float *x0 = nullptr, *C = nullptr, *c = nullptr, *F = nullptr, *f = nullptr;
    for (int i = 0; i < n_in; ++i) {
        switch (in_sizes[i]) {
            case BB * NS:                 x0 = (const float*)d_in[i]; break;  // 24576
            case TT * BB * NSC * NSC:     C  = (const float*)d_in[i]; break;  // 26214400
            case TT * BB * NSC:           c  = (const float*)d_in[i]; break;  // 1638400
            case TT * BB * NS * NSC:      F  = (const float*)d_in[i]; break;  // 19660800
            case TT * BB * NS:            f  = (const float*)d_in[i]; break;  // 614400
        }
    }

    const int blocks = BB / WPB;          // 512
    const int threads = 32 * WPB;         // 128
    const int gth = 256;
    const int gbl = (TT * BB * 16 + gth - 1) / gth;

    for (int it = 0; it < 3; ++it) {
        riccati_kernel<<<blocks, threads>>>(C, c, F, f);
        rollout_kernel<<<blocks, threads>>>(C, c, F, f, x0, it > 0 ? 1 : 0);
        select_kernel<<<(BB + 255) / 256, 256>>>();
        gather_kernel<<<gbl, gth>>>((float*)d_out, it == 2 ? 1 : 0);
    }
}

// round 2
// speedup vs baseline: 1.5514x; 1.5514x over previous
#include <cuda_runtime.h>

#define NS  12
#define NC  4
#define NSC 16
#define TT  50
#define BB  2048
#define NLS 5
#define WPB 2   // warps (batch elements) per block

// scratch: taus_all [a][t][b][16]
__device__ float g_taus[NLS * TT * BB * 16];

// per-warp smem layout (floats)
#define OFF_F    0      // 192
#define OFF_Q    192    // 256  (rollout: C)
#define OFF_q    448    // 16   (rollout: c)
#define OFF_f    464    // 16 (12 used, pad)
#define OFF_V    480    // 144  (rollout: tau 80 @480, part 80 @560, x 60 @640)
#define OFF_v    624    // 12
#define OFF_W    640    // 192
#define OFF_g    832    // 12  -> work end 844, pad to 848
#define OFF_K    848    // 2600 (50*52)
#define OFF_UN   3448   // 200  (50*4)
#define WARP_FLOATS 3648

struct Pref { float4 C0, C1, F0, F1, c4, f4; };

__device__ __forceinline__ void issue_loads(Pref& p,
    const float* __restrict__ gC, const float* __restrict__ gc,
    const float* __restrict__ gF, const float* __restrict__ gf,
    int base, int lane)
{
    const float4* Cp = reinterpret_cast<const float4*>(gC) + (size_t)base * 64;
    p.C0 = Cp[lane];
    p.C1 = Cp[lane + 32];
    const float4* Fp = reinterpret_cast<const float4*>(gF) + (size_t)base * 48;
    p.F0 = Fp[lane];
    if (lane < 16) p.F1 = Fp[lane + 32];
    if (lane < 4)  p.c4 = reinterpret_cast<const float4*>(gc)[(size_t)base * 4 + lane];
    if (lane < 3)  p.f4 = reinterpret_cast<const float4*>(gf)[(size_t)base * 3 + lane];
}

__device__ __forceinline__ void commit_loads(const Pref& p,
    float* sQ, float* sF, float* sq, float* sf, int lane)
{
    reinterpret_cast<float4*>(sQ)[lane]      = p.C0;
    reinterpret_cast<float4*>(sQ)[lane + 32] = p.C1;
    reinterpret_cast<float4*>(sF)[lane]      = p.F0;
    if (lane < 16) reinterpret_cast<float4*>(sF)[lane + 32] = p.F1;
    if (lane < 4)  reinterpret_cast<float4*>(sq)[lane] = p.c4;
    if (lane < 3)  reinterpret_cast<float4*>(sf)[lane] = p.f4;
}

// ============================================================================
// Fully fused iLQR: one warp per batch element does all 3 LQR iterations.
// ============================================================================
__global__ void __launch_bounds__(32 * WPB) ilqr_fused_kernel(
    const float* __restrict__ gC, const float* __restrict__ gc,
    const float* __restrict__ gF, const float* __restrict__ gf,
    const float* __restrict__ gx0, float* __restrict__ out)
{
    __shared__ __align__(16) float smem[WPB][WARP_FLOATS];
    const int w    = threadIdx.x >> 5;
    const int lane = threadIdx.x & 31;
    const int b    = blockIdx.x * WPB + w;

    float* S      = smem[w];
    float* sF     = S + OFF_F;
    float* sQ     = S + OFF_Q;   // doubles as sC in rollout
    float* sq     = S + OFF_q;   // doubles as sc
    float* sf     = S + OFF_f;
    float* sV     = S + OFF_V;
    float* sv     = S + OFF_v;
    float* sW     = S + OFF_W;
    float* sg     = S + OFF_g;
    float* sKall  = S + OFF_K;
    float* sUnom  = S + OFF_UN;
    // rollout aliases
    float* sTau  = S + 480;  // 80
    float* sPart = S + 560;  // 80
    float* sX    = S + 640;  // 60

    const int j = lane & 15;
    const int h = lane >> 4;

    // u_nom = 0
    for (int idx = lane; idx < 200; idx += 32) sUnom[idx] = 0.f;
    __syncwarp();

    for (int it = 0; it < 3; ++it) {
        const bool final_it = (it == 2);

        // ==================== Backward Riccati ====================
        // init V, v = 0
#pragma unroll
        for (int r = 0; r < 5; ++r) { int idx = lane + 32 * r; if (idx < 144) sV[idx] = 0.f; }
        if (lane < 12) sv[lane] = 0.f;

        Pref p;
        issue_loads(p, gC, gc, gF, gf, (TT - 1) * BB + b, lane);

        for (int t = TT - 1; t >= 0; --t) {
            __syncwarp();
            commit_loads(p, sQ, sF, sq, sf, lane);
            __syncwarp();
            if (t > 0) issue_loads(p, gC, gc, gF, gf, (t - 1) * BB + b, lane);

            float* sK = sKall + t * 52;

            // Phase 1: W = V F ; g = V f + v
            {
                float acc[6] = {0.f, 0.f, 0.f, 0.f, 0.f, 0.f};
#pragma unroll
                for (int m = 0; m < 12; ++m) {
                    float Fmj = sF[m * 16 + j];
#pragma unroll
                    for (int kk = 0; kk < 6; ++kk)
                        acc[kk] += sV[(h * 6 + kk) * 12 + m] * Fmj;
                }
#pragma unroll
                for (int kk = 0; kk < 6; ++kk) sW[(h * 6 + kk) * 16 + j] = acc[kk];
                if (lane < 12) {
                    float g = sv[lane];
#pragma unroll
                    for (int m = 0; m < 12; ++m) g += sV[lane * 12 + m] * sf[m];
                    sg[lane] = g;
                }
            }
            __syncwarp();

            // Phase 2: Q += F^T W ; q += F^T g
            {
                float acc[8] = {0.f, 0.f, 0.f, 0.f, 0.f, 0.f, 0.f, 0.f};
#pragma unroll
                for (int k = 0; k < 12; ++k) {
                    float Wkj = sW[k * 16 + j];
#pragma unroll
                    for (int ii = 0; ii < 8; ++ii)
                        acc[ii] += sF[k * 16 + (h * 8 + ii)] * Wkj;
                }
#pragma unroll
                for (int ii = 0; ii < 8; ++ii) sQ[(h * 8 + ii) * 16 + j] += acc[ii];
                if (lane < 16) {
                    float qa = sq[lane];
#pragma unroll
                    for (int k = 0; k < 12; ++k) qa += sF[k * 16 + lane] * sg[k];
                    sq[lane] = qa;
                }
            }
            __syncwarp();

            // Phase 3: solve Quu * sol = [Qux | qu], K = -sol
            {
                float A[4][4], r[4];
                const int col = (lane < 13) ? lane : 12;
#pragma unroll
                for (int u = 0; u < 4; ++u) {
#pragma unroll
                    for (int w2 = 0; w2 < 4; ++w2) A[u][w2] = sQ[(12 + u) * 16 + 12 + w2];
                    r[u] = (col < 12) ? sQ[(12 + u) * 16 + col] : sq[12 + u];
                }
#pragma unroll
                for (int pp = 0; pp < 4; ++pp) {
                    float inv = 1.0f / A[pp][pp];
                    r[pp] *= inv;
#pragma unroll
                    for (int w2 = 0; w2 < 4; ++w2) if (w2 > pp) A[pp][w2] *= inv;
#pragma unroll
                    for (int u = 0; u < 4; ++u) if (u > pp) {
                        float mu = A[u][pp];
                        r[u] -= mu * r[pp];
#pragma unroll
                        for (int w2 = 0; w2 < 4; ++w2) if (w2 > pp) A[u][w2] -= mu * A[pp][w2];
                    }
                }
#pragma unroll
                for (int pp = 3; pp >= 1; --pp)
#pragma unroll
                    for (int u = 0; u < 4; ++u) if (u < pp) r[u] -= A[u][pp] * r[pp];
                if (lane < 13) {
#pragma unroll
                    for (int u = 0; u < 4; ++u) sK[u * 13 + lane] = -r[u];
                }
            }
            __syncwarp();

            // Phase 4: M = Qxx + Qxu K ; V = 0.5(M + M^T) ; v = qx + K^T qu
            {
#pragma unroll
                for (int r2 = 0; r2 < 5; ++r2) {
                    int idx = lane + 32 * r2;
                    if (idx < 144) {
                        int i = idx / 12, jj = idx - i * 12;
                        float m = sQ[i * 16 + jj];
#pragma unroll
                        for (int u = 0; u < 4; ++u) m += sQ[i * 16 + 12 + u] * sK[u * 13 + jj];
                        sW[idx] = m;
                    }
                }
                __syncwarp();
#pragma unroll
                for (int r2 = 0; r2 < 5; ++r2) {
                    int idx = lane + 32 * r2;
                    if (idx < 144) {
                        int i = idx / 12, jj = idx - i * 12;
                        sV[idx] = 0.5f * (sW[idx] + sW[jj * 12 + i]);
                    }
                }
                if (lane < 12) {
                    float vn = sq[lane];
#pragma unroll
                    for (int u = 0; u < 4; ++u) vn += sK[u * 13 + lane] * sq[12 + u];
                    sv[lane] = vn;
                }
            }
        }
        __syncwarp();

        // ==================== Forward rollout (5 alphas) ====================
        if (lane < 12) {
            float x = gx0[b * 12 + lane];
#pragma unroll
            for (int a = 0; a < 5; ++a) sX[a * 12 + lane] = x;
        }
        float myCost = 0.f;

        issue_loads(p, gC, gc, gF, gf, 0 * BB + b, lane);

        for (int t = 0; t < TT; ++t) {
            __syncwarp();
            commit_loads(p, sQ, sF, sq, sf, lane);   // sQ==sC, sq==sc
            __syncwarp();
            if (t < TT - 1) issue_loads(p, gC, gc, gF, gf, (t + 1) * BB + b, lane);

            const float* sK = sKall + t * 52;

            // controls: lane = a*4+u, lane<20
            if (lane < 20) {
                int a = lane >> 2, u = lane & 3;
                float ul = sK[u * 13 + 12];
#pragma unroll
                for (int s = 0; s < 12; ++s) ul += sK[u * 13 + s] * sX[a * 12 + s];
                float alpha = 1.0f / (float)(1 << a);
                float uu = (1.0f - alpha) * sUnom[t * 4 + u] + alpha * ul;
                uu = fminf(1.0f, fmaxf(-1.0f, uu));
                sTau[a * 16 + 12 + u] = uu;
            }
            // copy x into tau
#pragma unroll
            for (int r = 0; r < 2; ++r) {
                int idx = lane + 32 * r;
                if (idx < 60) {
                    int a = idx / 12, s = idx - a * 12;
                    sTau[a * 16 + s] = sX[idx];
                }
            }
            __syncwarp();

            // cost partials + taus writes
#pragma unroll
            for (int r = 0; r < 3; ++r) {
                int idx = lane + 32 * r;
                if (idx < 80) {
                    int a = idx >> 4, jj = idx & 15;
                    float s = 0.f;
#pragma unroll
                    for (int i = 0; i < 16; ++i) s += sTau[a * 16 + i] * sQ[i * 16 + jj];
                    float ta = sTau[a * 16 + jj];
                    sPart[idx] = ta * (0.5f * s + sq[jj]);
                    if (final_it || jj >= 12)
                        g_taus[((size_t)(a * TT + t) * BB + b) * 16 + jj] = ta;
                }
            }
            // x_next
            float xn0 = 0.f, xn1 = 0.f;
            {
                int idx = lane;
                if (idx < 60) {
                    int a = idx / 12, s = idx - a * 12;
                    float v = sf[s];
#pragma unroll
                    for (int jj = 0; jj < 16; ++jj) v += sF[s * 16 + jj] * sTau[a * 16 + jj];
                    xn0 = v;
                }
                idx = lane + 32;
                if (idx < 60) {
                    int a = idx / 12, s = idx - a * 12;
                    float v = sf[s];
#pragma unroll
                    for (int jj = 0; jj < 16; ++jj) v += sF[s * 16 + jj] * sTau[a * 16 + jj];
                    xn1 = v;
                }
            }
            __syncwarp();

            if (lane < 5) {
                float cs = 0.f;
#pragma unroll
                for (int jj = 0; jj < 16; ++jj) cs += sPart[lane * 16 + jj];
                myCost += cs;
            }
            if (lane < 60) sX[lane] = xn0;
            if (lane + 32 < 60) sX[lane + 32] = xn1;
        }
        __threadfence_block();
        __syncwarp();

        // ==================== per-warp argmin over alphas ====================
        int bi = 0;
        {
            float bc = __shfl_sync(0xffffffffu, myCost, 0);
#pragma unroll
            for (int a = 1; a < NLS; ++a) {
                float ca = __shfl_sync(0xffffffffu, myCost, a);
                if (ca < bc) { bc = ca; bi = a; }
            }
        }

        // ==================== gather: u_nom update / final output ====================
        if (!final_it) {
            for (int idx = lane; idx < 200; idx += 32) {
                int t = idx >> 2, u = idx & 3;
                sUnom[idx] = g_taus[((size_t)(bi * TT + t) * BB + b) * 16 + 12 + u];
            }
        } else {
            for (int idx = lane; idx < 800; idx += 32) {
                int t = idx >> 4, i = idx & 15;
                out[((size_t)t * BB + b) * 16 + i] =
                    g_taus[((size_t)(bi * TT + t) * BB + b) * 16 + i];
            }
        }
        __syncwarp();
    }
}

// ============================================================================
extern "C" void kernel_launch(void* const* d_in, const int* in_sizes, int n_in,
                              void* d_out, int out_size)
{
    const float *x0 = nullptr, *C = nullptr, *c = nullptr, *F = nullptr, *f = nullptr;
    for (int i = 0; i < n_in; ++i) {
        switch (in_sizes[i]) {
            case BB * NS:             x0 = (const float*)d_in[i]; break;
            case TT * BB * NSC * NSC: C  = (const float*)d_in[i]; break;
            case TT * BB * NSC:       c  = (const float*)d_in[i]; break;
            case TT * BB * NS * NSC:  F  = (const float*)d_in[i]; break;
            case TT * BB * NS:        f  = (const float*)d_in[i]; break;
        }
    }
    ilqr_fused_kernel<<<BB / WPB, 32 * WPB>>>(C, c, F, f, x0, (float*)d_out);
}